// round 1
// baseline (speedup 1.0000x reference)
#include <cuda_runtime.h>
#include <math.h>
#include <stdint.h>

#define D    1024
#define DFF  4096
#define E    8
#define TOK  8192            // B*S = 4*2048
#define BM   128
#define BN   128
#define BK   8
#define MAXROWS (2*TOK + E*BM)   // 17408, every expert segment padded to BM
#define NTILES_ROW (MAXROWS/BM)  // 136

// ---------------- scratch (__device__ globals; no allocations allowed) ----------------
__device__ int   g_eid[TOK*2];          // expert id per (token,k)
__device__ float g_gw[TOK*2];           // gate weight per (token,k)
__device__ int   g_counts[E];
__device__ int   g_off[E+1];            // padded segment offsets
__device__ int   g_cursor[E];
__device__ int   g_total;               // total padded rows
__device__ int   g_slot_token[MAXROWS];
__device__ float g_slot_w[MAXROWS];
__device__ int   g_slot_of[TOK*2];      // slot index for each (token,k)
__device__ float g_usage[E];
__device__ float g_h[(size_t)MAXROWS*DFF];  // gelu(x@W1+b1), 285MB
__device__ float g_y[(size_t)MAXROWS*D];    // h@W2+b2, 71MB

// ---------------- init ----------------
__global__ void k_init() {
    int i = blockIdx.x*blockDim.x + threadIdx.x;
    if (i < MAXROWS) { g_slot_token[i] = 0; g_slot_w[i] = 0.f; }
    if (i < E) { g_counts[i] = 0; g_usage[i] = 0.f; }
}

// ---------------- gating: warp per token ----------------
__global__ __launch_bounds__(256) void k_gate(const float* __restrict__ x,
                                              const float* __restrict__ Wg) {
    __shared__ float sWg[E*D];
    for (int i = threadIdx.x; i < E*D; i += blockDim.x) sWg[i] = Wg[i];
    __syncthreads();
    int warp = threadIdx.x >> 5, lane = threadIdx.x & 31;
    int t = blockIdx.x * 8 + warp;
    if (t >= TOK) return;
    const float* xr = x + (size_t)t * D;
    float acc[E];
    #pragma unroll
    for (int e = 0; e < E; e++) acc[e] = 0.f;
    for (int d = lane; d < D; d += 32) {
        float xv = xr[d];
        #pragma unroll
        for (int e = 0; e < E; e++) acc[e] += xv * sWg[e*D + d];
    }
    #pragma unroll
    for (int e = 0; e < E; e++)
        #pragma unroll
        for (int o = 16; o > 0; o >>= 1)
            acc[e] += __shfl_xor_sync(0xffffffffu, acc[e], o);
    if (lane == 0) {
        // top-2, lowest index wins ties (matches jax.lax.top_k)
        int i0 = 0; float v0 = acc[0];
        #pragma unroll
        for (int e = 1; e < E; e++) if (acc[e] > v0) { v0 = acc[e]; i0 = e; }
        int i1 = -1; float v1 = -INFINITY;
        #pragma unroll
        for (int e = 0; e < E; e++) if (e != i0 && acc[e] > v1) { v1 = acc[e]; i1 = e; }
        float ex = expf(v1 - v0);
        float inv = 1.f / (1.f + ex);
        float w0 = inv, w1 = ex * inv;
        g_eid[t*2]   = i0; g_eid[t*2+1] = i1;
        g_gw[t*2]    = w0; g_gw[t*2+1]  = w1;
        atomicAdd(&g_counts[i0], 1); atomicAdd(&g_counts[i1], 1);
        atomicAdd(&g_usage[i0], w0); atomicAdd(&g_usage[i1], w1);
    }
}

// ---------------- offsets + lb_loss ----------------
__global__ void k_offsets(float* loss_out, int write_loss) {
    int off = 0;
    g_off[0] = 0;
    for (int e = 0; e < E; e++) {
        g_cursor[e] = off;
        off += (g_counts[e] + BM - 1) / BM * BM;
        g_off[e+1] = off;
    }
    g_total = off;
    if (write_loss) {
        float u[E]; float mean = 0.f;
        for (int e = 0; e < E; e++) { u[e] = g_usage[e] / (float)TOK; mean += u[e]; }
        mean /= (float)E;
        float var = 0.f;
        for (int e = 0; e < E; e++) { float d = u[e] - mean; var += d * d; }
        var /= (float)(E - 1);          // ddof=1
        loss_out[0] = var * 0.01f;
    }
}

// ---------------- scatter tokens into expert segments ----------------
__global__ void k_scatter() {
    int i = blockIdx.x*blockDim.x + threadIdx.x;
    if (i >= TOK*2) return;
    int e = g_eid[i];
    int pos = atomicAdd(&g_cursor[e], 1);
    g_slot_token[pos] = i >> 1;
    g_slot_w[pos] = g_gw[i];
    g_slot_of[i] = pos;
}

// ---------------- GEMM1: h = gelu(x[slot] @ W1[e] + b1[e]) ----------------
// tiles: BMxBN, K=D. A gathered by slot_token. B row-major [D, DFF].
__global__ __launch_bounds__(256) void k_gemm1(const float* __restrict__ x,
                                               const float* __restrict__ W1,
                                               const float* __restrict__ b1) {
    int row0 = blockIdx.y * BM;
    if (row0 >= g_total) return;
    int e = 0;
    #pragma unroll
    for (int i = 1; i < E; i++) if (row0 >= g_off[i]) e = i;
    const float* Bg = W1 + (size_t)e * D * DFF + blockIdx.x * BN;

    __shared__ float As[BK][BM + 4];   // padded stride 132 (16B-aligned rows)
    __shared__ float Bs[BK][BN];

    int tid = threadIdx.x;
    int a_m = tid >> 1;                // 0..127
    int a_k = (tid & 1) * 4;           // 0 or 4
    const float* arow = x + (size_t)g_slot_token[row0 + a_m] * D + a_k;
    int b_k = tid >> 5;                // 0..7
    int b_n = (tid & 31) * 4;
    int ty = tid >> 4, tx = tid & 15;

    float acc[8][8] = {};
    for (int k0 = 0; k0 < D; k0 += BK) {
        float4 av = *(const float4*)(arow + k0);
        As[a_k+0][a_m] = av.x; As[a_k+1][a_m] = av.y;
        As[a_k+2][a_m] = av.z; As[a_k+3][a_m] = av.w;
        *(float4*)&Bs[b_k][b_n] = *(const float4*)(Bg + (size_t)(k0 + b_k) * DFF + b_n);
        __syncthreads();
        #pragma unroll
        for (int k = 0; k < BK; k++) {
            float4 a0 = *(const float4*)&As[k][ty*8];
            float4 a1 = *(const float4*)&As[k][ty*8 + 4];
            float4 b0 = *(const float4*)&Bs[k][tx*8];
            float4 b1v = *(const float4*)&Bs[k][tx*8 + 4];
            float ra[8] = {a0.x,a0.y,a0.z,a0.w,a1.x,a1.y,a1.z,a1.w};
            float rb[8] = {b0.x,b0.y,b0.z,b0.w,b1v.x,b1v.y,b1v.z,b1v.w};
            #pragma unroll
            for (int i = 0; i < 8; i++)
                #pragma unroll
                for (int j = 0; j < 8; j++)
                    acc[i][j] += ra[i] * rb[j];
        }
        __syncthreads();
    }
    int n0 = blockIdx.x * BN;
    #pragma unroll
    for (int i = 0; i < 8; i++) {
        int row = row0 + ty*8 + i;
        float* hrow = g_h + (size_t)row * DFF + n0;
        #pragma unroll
        for (int j = 0; j < 8; j++) {
            int n = tx*8 + j;
            float v = acc[i][j] + b1[e*DFF + n0 + n];
            hrow[n] = 0.5f * v * (1.f + erff(v * 0.70710678118654752f));   // exact gelu
        }
    }
}

// ---------------- GEMM2: y = h @ W2[e] + b2[e] ----------------
__global__ __launch_bounds__(256) void k_gemm2(const float* __restrict__ W2,
                                               const float* __restrict__ b2) {
    int row0 = blockIdx.y * BM;
    if (row0 >= g_total) return;
    int e = 0;
    #pragma unroll
    for (int i = 1; i < E; i++) if (row0 >= g_off[i]) e = i;
    const float* Bg = W2 + (size_t)e * DFF * D + blockIdx.x * BN;

    __shared__ float As[BK][BM + 4];
    __shared__ float Bs[BK][BN];

    int tid = threadIdx.x;
    int a_m = tid >> 1;
    int a_k = (tid & 1) * 4;
    const float* arow = g_h + (size_t)(row0 + a_m) * DFF + a_k;
    int b_k = tid >> 5;
    int b_n = (tid & 31) * 4;
    int ty = tid >> 4, tx = tid & 15;

    float acc[8][8] = {};
    for (int k0 = 0; k0 < DFF; k0 += BK) {
        float4 av = *(const float4*)(arow + k0);
        As[a_k+0][a_m] = av.x; As[a_k+1][a_m] = av.y;
        As[a_k+2][a_m] = av.z; As[a_k+3][a_m] = av.w;
        *(float4*)&Bs[b_k][b_n] = *(const float4*)(Bg + (size_t)(k0 + b_k) * D + b_n);
        __syncthreads();
        #pragma unroll
        for (int k = 0; k < BK; k++) {
            float4 a0 = *(const float4*)&As[k][ty*8];
            float4 a1 = *(const float4*)&As[k][ty*8 + 4];
            float4 b0 = *(const float4*)&Bs[k][tx*8];
            float4 b1v = *(const float4*)&Bs[k][tx*8 + 4];
            float ra[8] = {a0.x,a0.y,a0.z,a0.w,a1.x,a1.y,a1.z,a1.w};
            float rb[8] = {b0.x,b0.y,b0.z,b0.w,b1v.x,b1v.y,b1v.z,b1v.w};
            #pragma unroll
            for (int i = 0; i < 8; i++)
                #pragma unroll
                for (int j = 0; j < 8; j++)
                    acc[i][j] += ra[i] * rb[j];
        }
        __syncthreads();
    }
    int n0 = blockIdx.x * BN;
    #pragma unroll
    for (int i = 0; i < 8; i++) {
        int row = row0 + ty*8 + i;
        float* yrow = g_y + (size_t)row * D + n0;
        #pragma unroll
        for (int j = 0; j < 8; j++) {
            int n = tx*8 + j;
            yrow[n] = acc[i][j] + b2[e*D + n0 + n];
        }
    }
}

// ---------------- combine: out[t] = w0*y[s0] + w1*y[s1] (deterministic) ----------------
__global__ void k_combine(float* __restrict__ out) {
    int i = blockIdx.x*blockDim.x + threadIdx.x;
    if (i >= TOK*D) return;
    int t = i >> 10;           // /D
    int d = i & 1023;          // %D
    int s0 = g_slot_of[t*2], s1 = g_slot_of[t*2+1];
    out[i] = g_gw[t*2]   * g_y[(size_t)s0*D + d]
           + g_gw[t*2+1] * g_y[(size_t)s1*D + d];
}

// ---------------- launch ----------------
extern "C" void kernel_launch(void* const* d_in, const int* in_sizes, int n_in,
                              void* d_out, int out_size) {
    const float* x  = (const float*)d_in[0];
    const float* Wg = (const float*)d_in[1];
    const float* W1 = (const float*)d_in[2];
    const float* b1 = (const float*)d_in[3];
    const float* W2 = (const float*)d_in[4];
    const float* b2 = (const float*)d_in[5];
    float* out = (float*)d_out;

    k_init<<<(MAXROWS + 255)/256, 256>>>();
    k_gate<<<TOK/8, 256>>>(x, Wg);
    k_offsets<<<1,1>>>(out + (size_t)TOK*D, (out_size > TOK*D) ? 1 : 0);
    k_scatter<<<(TOK*2 + 255)/256, 256>>>();
    dim3 g1(DFF/BN, NTILES_ROW);
    k_gemm1<<<g1, 256>>>(x, W1, b1);
    dim3 g2(D/BN, NTILES_ROW);
    k_gemm2<<<g2, 256>>>(W2, b2);
    k_combine<<<(TOK*D + 255)/256, 256>>>(out);
}

// round 3
// speedup vs baseline: 2.3224x; 2.3224x over previous
#include <cuda_runtime.h>
#include <cuda_bf16.h>
#include <math.h>
#include <stdint.h>

#define D    1024
#define DFF  4096
#define E    8
#define TOK  8192
#define BM   128
#define BN   128
#define BK   32              // bf16 elems per K chunk
#define STAGES 4
#define ROWB 80              // padded row stride bytes (32 bf16 = 64B data + 16B pad)
#define MATB (128*ROWB)      // 10240 bytes per matrix tile
#define STGB (4*MATB)        // 40960: Ah, Al, Bh, Bl
#define SMEM_BYTES (STAGES*STGB)   // 163840
#define MAXROWS (2*TOK + E*BM)     // 17408
#define NROWT (MAXROWS/BM)         // 136

// ---------------- scratch ----------------
__device__ int   g_eid[TOK*2];
__device__ float g_gw[TOK*2];
__device__ int   g_counts[E];
__device__ int   g_off[E+1];
__device__ int   g_cursor[E];
__device__ int   g_total;
__device__ int   g_slot_token[MAXROWS];
__device__ int   g_slot_of[TOK*2];
__device__ float g_usage[E];
__device__ __nv_bfloat16 g_xhi[TOK*D],  g_xlo[TOK*D];
__device__ __nv_bfloat16 g_w1hi[E*DFF*D], g_w1lo[E*DFF*D];   // [E][DFF][D]
__device__ __nv_bfloat16 g_w2hi[E*D*DFF], g_w2lo[E*D*DFF];   // [E][D][DFF]
__device__ __nv_bfloat16 g_hhi[(size_t)MAXROWS*DFF], g_hlo[(size_t)MAXROWS*DFF];
__device__ float g_y[(size_t)MAXROWS*D];

// ---------------- helpers ----------------
__device__ __forceinline__ uint32_t smem_u32(const void* p) {
    uint32_t a;
    asm("{ .reg .u64 t; cvta.to.shared.u64 t, %1; cvt.u32.u64 %0, t; }" : "=r"(a) : "l"(p));
    return a;
}
#define CPA(dst, src) asm volatile("cp.async.cg.shared.global [%0], [%1], 16;" :: "r"(dst), "l"(src) : "memory")
#define CPCOMMIT()    asm volatile("cp.async.commit_group;" ::: "memory")
#define CPWAIT(n)     asm volatile("cp.async.wait_group %0;" :: "n"(n) : "memory")
#define MMA(c, a, b) asm volatile( \
    "mma.sync.aligned.m16n8k16.row.col.f32.bf16.bf16.f32 " \
    "{%0,%1,%2,%3},{%4,%5,%6,%7},{%8,%9},{%0,%1,%2,%3};" \
    : "+f"((c)[0]),"+f"((c)[1]),"+f"((c)[2]),"+f"((c)[3]) \
    : "r"((a)[0]),"r"((a)[1]),"r"((a)[2]),"r"((a)[3]),"r"((b)[0]),"r"((b)[1]))

// ---------------- init ----------------
__global__ void k_init() {
    int i = blockIdx.x*blockDim.x + threadIdx.x;
    if (i < MAXROWS) g_slot_token[i] = 0;
    if (i < E) { g_counts[i] = 0; g_usage[i] = 0.f; }
}

// ---------------- gating ----------------
__global__ __launch_bounds__(256) void k_gate(const float* __restrict__ x,
                                              const float* __restrict__ Wg) {
    __shared__ float sWg[E*D];
    for (int i = threadIdx.x; i < E*D; i += blockDim.x) sWg[i] = Wg[i];
    __syncthreads();
    int warp = threadIdx.x >> 5, lane = threadIdx.x & 31;
    int t = blockIdx.x * 8 + warp;
    if (t >= TOK) return;
    const float* xr = x + (size_t)t * D;
    float acc[E];
    #pragma unroll
    for (int e = 0; e < E; e++) acc[e] = 0.f;
    for (int d = lane; d < D; d += 32) {
        float xv = xr[d];
        #pragma unroll
        for (int e = 0; e < E; e++) acc[e] += xv * sWg[e*D + d];
    }
    #pragma unroll
    for (int e = 0; e < E; e++)
        #pragma unroll
        for (int o = 16; o > 0; o >>= 1)
            acc[e] += __shfl_xor_sync(0xffffffffu, acc[e], o);
    if (lane == 0) {
        int i0 = 0; float v0 = acc[0];
        #pragma unroll
        for (int e = 1; e < E; e++) if (acc[e] > v0) { v0 = acc[e]; i0 = e; }
        int i1 = -1; float v1 = -INFINITY;
        #pragma unroll
        for (int e = 0; e < E; e++) if (e != i0 && acc[e] > v1) { v1 = acc[e]; i1 = e; }
        float ex = expf(v1 - v0);
        float inv = 1.f / (1.f + ex);
        g_eid[t*2] = i0; g_eid[t*2+1] = i1;
        g_gw[t*2]  = inv; g_gw[t*2+1] = ex * inv;
        atomicAdd(&g_counts[i0], 1); atomicAdd(&g_counts[i1], 1);
        atomicAdd(&g_usage[i0], inv); atomicAdd(&g_usage[i1], ex*inv);
    }
}

// ---------------- offsets + lb loss ----------------
__global__ void k_offsets(float* loss_out, int write_loss) {
    int off = 0;
    g_off[0] = 0;
    for (int e = 0; e < E; e++) {
        g_cursor[e] = off;
        off += (g_counts[e] + BM - 1) / BM * BM;
        g_off[e+1] = off;
    }
    g_total = off;
    if (write_loss) {
        float u[E]; float mean = 0.f;
        for (int e = 0; e < E; e++) { u[e] = g_usage[e] / (float)TOK; mean += u[e]; }
        mean /= (float)E;
        float var = 0.f;
        for (int e = 0; e < E; e++) { float d = u[e] - mean; var += d * d; }
        var /= (float)(E - 1);
        loss_out[0] = var * 0.01f;
    }
}

// ---------------- scatter ----------------
__global__ void k_scatter() {
    int i = blockIdx.x*blockDim.x + threadIdx.x;
    if (i >= TOK*2) return;
    int e = g_eid[i];
    int pos = atomicAdd(&g_cursor[e], 1);
    g_slot_token[pos] = i >> 1;
    g_slot_of[i] = pos;
}

// ---------------- split x into bf16 hi/lo ----------------
__global__ void k_split_x(const float* __restrict__ x) {
    int i = (blockIdx.x*blockDim.x + threadIdx.x) * 4;
    if (i >= TOK*D) return;
    float4 v = *(const float4*)(x + i);
    __nv_bfloat162 h01 = __floats2bfloat162_rn(v.x, v.y);
    __nv_bfloat162 h23 = __floats2bfloat162_rn(v.z, v.w);
    float l0 = v.x - __bfloat162float(__low2bfloat16(h01));
    float l1 = v.y - __bfloat162float(__high2bfloat16(h01));
    float l2 = v.z - __bfloat162float(__low2bfloat16(h23));
    float l3 = v.w - __bfloat162float(__high2bfloat16(h23));
    __nv_bfloat162 lo01 = __floats2bfloat162_rn(l0, l1);
    __nv_bfloat162 lo23 = __floats2bfloat162_rn(l2, l3);
    uint2 ph = make_uint2(*(uint32_t*)&h01, *(uint32_t*)&h23);
    uint2 pl = make_uint2(*(uint32_t*)&lo01, *(uint32_t*)&lo23);
    *(uint2*)((char*)g_xhi + (size_t)i*2) = ph;
    *(uint2*)((char*)g_xlo + (size_t)i*2) = pl;
}

// ---------------- transpose + split weights ----------------
__global__ void k_tsplit(const float* __restrict__ W, int R, int C, int which) {
    __shared__ float t[32][33];
    int e = blockIdx.z;
    int c0 = blockIdx.x * 32, r0 = blockIdx.y * 32;
    int tx = threadIdx.x, ty = threadIdx.y;
    const float* in = W + (size_t)e * R * C;
    #pragma unroll
    for (int i = ty; i < 32; i += 8)
        t[i][tx] = in[(size_t)(r0 + i) * C + c0 + tx];
    __syncthreads();
    __nv_bfloat16* oh = which ? g_w2hi : g_w1hi;
    __nv_bfloat16* ol = which ? g_w2lo : g_w1lo;
    size_t ob = (size_t)e * C * R;
    #pragma unroll
    for (int i = ty; i < 32; i += 8) {
        float v = t[tx][i];
        size_t oi = ob + (size_t)(c0 + i) * R + r0 + tx;
        __nv_bfloat16 h = __float2bfloat16_rn(v);
        oh[oi] = h;
        ol[oi] = __float2bfloat16_rn(v - __bfloat162float(h));
    }
}

// ================= mma.sync GEMMs =================
// stage layout (per stage): [Ah 10240][Al 10240][Bh 10240][Bl 10240]
// A tile: 128 rows x 32 bf16, row stride 80B. B tile: [N=128][K=32] same.

__global__ void __launch_bounds__(256, 1) k_gemm1_mma(const float* __restrict__ b1) {
    extern __shared__ __align__(128) char smem[];
    __shared__ int stok[BM];
    const int tid = threadIdx.x, wid = tid >> 5, lane = tid & 31;
    const int g = lane >> 2, t4 = lane & 3;
    const int row0 = blockIdx.y * BM;
    if (row0 >= g_total) return;
    int e = 0;
    #pragma unroll
    for (int i = 1; i < E; i++) if (row0 >= g_off[i]) e = i;
    const int n0 = blockIdx.x * BN;
    const int wm = (wid >> 2) * 64, wn = (wid & 3) * 32;

    if (tid < BM) stok[tid] = g_slot_token[row0 + tid];
    __syncthreads();
    const uint32_t sb = smem_u32(smem);

    #define STAGE(st, c) do { \
        uint32_t base = sb + (st)*STGB; \
        int k0 = (c)*BK; \
        _Pragma("unroll") \
        for (int i = 0; i < 2; i++) { \
            int id = tid + i*256, row = id >> 2, c4 = id & 3; \
            size_t so = ((size_t)stok[row]*D + k0)*2 + c4*16; \
            uint32_t dsto = base + row*ROWB + c4*16; \
            CPA(dsto,        (const char*)g_xhi + so); \
            CPA(dsto + MATB, (const char*)g_xlo + so); \
        } \
        _Pragma("unroll") \
        for (int i = 0; i < 2; i++) { \
            int id = tid + i*256, row = id >> 2, c4 = id & 3; \
            size_t so = (((size_t)e*DFF + n0 + row)*D + k0)*2 + c4*16; \
            uint32_t dsto = base + 2*MATB + row*ROWB + c4*16; \
            CPA(dsto,        (const char*)g_w1hi + so); \
            CPA(dsto + MATB, (const char*)g_w1lo + so); \
        } \
    } while (0)

    const int NC = D / BK;   // 32
    #pragma unroll
    for (int c = 0; c < STAGES-1; c++) { STAGE(c, c); CPCOMMIT(); }

    float acc[4][4][4] = {};
    for (int c = 0; c < NC; c++) {
        CPWAIT(STAGES-2);
        __syncthreads();
        if (c + STAGES-1 < NC) STAGE((c + STAGES-1) & (STAGES-1), c + STAGES-1);
        CPCOMMIT();
        const char* sp = smem + (c & (STAGES-1)) * STGB;
        #pragma unroll
        for (int ks = 0; ks < 2; ks++) {
            uint32_t ah[4][4], al[4][4], bh[4][2], bl[4][2];
            #pragma unroll
            for (int mt = 0; mt < 4; mt++) {
                const char* p = sp + (wm + mt*16 + g)*ROWB + ks*32 + t4*4;
                ah[mt][0] = *(const uint32_t*)(p);
                ah[mt][1] = *(const uint32_t*)(p + 8*ROWB);
                ah[mt][2] = *(const uint32_t*)(p + 16);
                ah[mt][3] = *(const uint32_t*)(p + 8*ROWB + 16);
                al[mt][0] = *(const uint32_t*)(p + MATB);
                al[mt][1] = *(const uint32_t*)(p + MATB + 8*ROWB);
                al[mt][2] = *(const uint32_t*)(p + MATB + 16);
                al[mt][3] = *(const uint32_t*)(p + MATB + 8*ROWB + 16);
            }
            #pragma unroll
            for (int nt = 0; nt < 4; nt++) {
                const char* p = sp + 2*MATB + (wn + nt*8 + g)*ROWB + ks*32 + t4*4;
                bh[nt][0] = *(const uint32_t*)(p);
                bh[nt][1] = *(const uint32_t*)(p + 16);
                bl[nt][0] = *(const uint32_t*)(p + MATB);
                bl[nt][1] = *(const uint32_t*)(p + MATB + 16);
            }
            #pragma unroll
            for (int mt = 0; mt < 4; mt++)
                #pragma unroll
                for (int nt = 0; nt < 4; nt++) {
                    MMA(acc[mt][nt], ah[mt], bh[nt]);
                    MMA(acc[mt][nt], ah[mt], bl[nt]);
                    MMA(acc[mt][nt], al[mt], bh[nt]);
                }
        }
    }

    // epilogue: bias + exact gelu + bf16 split store
    #pragma unroll
    for (int mt = 0; mt < 4; mt++) {
        #pragma unroll
        for (int nt = 0; nt < 4; nt++) {
            int col = n0 + wn + nt*8 + t4*2;
            float bi0 = __ldg(&b1[e*DFF + col]);
            float bi1 = __ldg(&b1[e*DFF + col + 1]);
            #pragma unroll
            for (int h = 0; h < 2; h++) {
                int row = row0 + wm + mt*16 + g + h*8;
                float v0 = acc[mt][nt][2*h]   + bi0;
                float v1 = acc[mt][nt][2*h+1] + bi1;
                float g0 = 0.5f * v0 * (1.f + erff(v0 * 0.7071067811865476f));
                float g1 = 0.5f * v1 * (1.f + erff(v1 * 0.7071067811865476f));
                __nv_bfloat162 hh = __floats2bfloat162_rn(g0, g1);
                float l0 = g0 - __bfloat162float(__low2bfloat16(hh));
                float l1 = g1 - __bfloat162float(__high2bfloat16(hh));
                __nv_bfloat162 ll = __floats2bfloat162_rn(l0, l1);
                size_t o = ((size_t)row * DFF + col) * 2;
                *(uint32_t*)((char*)g_hhi + o) = *(uint32_t*)&hh;
                *(uint32_t*)((char*)g_hlo + o) = *(uint32_t*)&ll;
            }
        }
    }
    #undef STAGE
}

__global__ void __launch_bounds__(256, 1) k_gemm2_mma(const float* __restrict__ b2) {
    extern __shared__ __align__(128) char smem[];
    const int tid = threadIdx.x, wid = tid >> 5, lane = tid & 31;
    const int g = lane >> 2, t4 = lane & 3;
    const int row0 = blockIdx.y * BM;
    if (row0 >= g_total) return;
    int e = 0;
    #pragma unroll
    for (int i = 1; i < E; i++) if (row0 >= g_off[i]) e = i;
    const int n0 = blockIdx.x * BN;
    const int wm = (wid >> 2) * 64, wn = (wid & 3) * 32;
    const uint32_t sb = smem_u32(smem);

    #define STAGE(st, c) do { \
        uint32_t base = sb + (st)*STGB; \
        int k0 = (c)*BK; \
        _Pragma("unroll") \
        for (int i = 0; i < 2; i++) { \
            int id = tid + i*256, row = id >> 2, c4 = id & 3; \
            size_t so = ((size_t)(row0 + row)*DFF + k0)*2 + c4*16; \
            uint32_t dsto = base + row*ROWB + c4*16; \
            CPA(dsto,        (const char*)g_hhi + so); \
            CPA(dsto + MATB, (const char*)g_hlo + so); \
        } \
        _Pragma("unroll") \
        for (int i = 0; i < 2; i++) { \
            int id = tid + i*256, row = id >> 2, c4 = id & 3; \
            size_t so = (((size_t)e*D + n0 + row)*DFF + k0)*2 + c4*16; \
            uint32_t dsto = base + 2*MATB + row*ROWB + c4*16; \
            CPA(dsto,        (const char*)g_w2hi + so); \
            CPA(dsto + MATB, (const char*)g_w2lo + so); \
        } \
    } while (0)

    const int NC = DFF / BK;   // 128
    #pragma unroll
    for (int c = 0; c < STAGES-1; c++) { STAGE(c, c); CPCOMMIT(); }

    float acc[4][4][4] = {};
    for (int c = 0; c < NC; c++) {
        CPWAIT(STAGES-2);
        __syncthreads();
        if (c + STAGES-1 < NC) STAGE((c + STAGES-1) & (STAGES-1), c + STAGES-1);
        CPCOMMIT();
        const char* sp = smem + (c & (STAGES-1)) * STGB;
        #pragma unroll
        for (int ks = 0; ks < 2; ks++) {
            uint32_t ah[4][4], al[4][4], bh[4][2], bl[4][2];
            #pragma unroll
            for (int mt = 0; mt < 4; mt++) {
                const char* p = sp + (wm + mt*16 + g)*ROWB + ks*32 + t4*4;
                ah[mt][0] = *(const uint32_t*)(p);
                ah[mt][1] = *(const uint32_t*)(p + 8*ROWB);
                ah[mt][2] = *(const uint32_t*)(p + 16);
                ah[mt][3] = *(const uint32_t*)(p + 8*ROWB + 16);
                al[mt][0] = *(const uint32_t*)(p + MATB);
                al[mt][1] = *(const uint32_t*)(p + MATB + 8*ROWB);
                al[mt][2] = *(const uint32_t*)(p + MATB + 16);
                al[mt][3] = *(const uint32_t*)(p + MATB + 8*ROWB + 16);
            }
            #pragma unroll
            for (int nt = 0; nt < 4; nt++) {
                const char* p = sp + 2*MATB + (wn + nt*8 + g)*ROWB + ks*32 + t4*4;
                bh[nt][0] = *(const uint32_t*)(p);
                bh[nt][1] = *(const uint32_t*)(p + 16);
                bl[nt][0] = *(const uint32_t*)(p + MATB);
                bl[nt][1] = *(const uint32_t*)(p + MATB + 16);
            }
            #pragma unroll
            for (int mt = 0; mt < 4; mt++)
                #pragma unroll
                for (int nt = 0; nt < 4; nt++) {
                    MMA(acc[mt][nt], ah[mt], bh[nt]);
                    MMA(acc[mt][nt], ah[mt], bl[nt]);
                    MMA(acc[mt][nt], al[mt], bh[nt]);
                }
        }
    }

    #pragma unroll
    for (int mt = 0; mt < 4; mt++) {
        #pragma unroll
        for (int nt = 0; nt < 4; nt++) {
            int col = n0 + wn + nt*8 + t4*2;
            float bi0 = __ldg(&b2[e*D + col]);
            float bi1 = __ldg(&b2[e*D + col + 1]);
            #pragma unroll
            for (int h = 0; h < 2; h++) {
                int row = row0 + wm + mt*16 + g + h*8;
                float2 v = make_float2(acc[mt][nt][2*h] + bi0, acc[mt][nt][2*h+1] + bi1);
                *(float2*)(g_y + (size_t)row * D + col) = v;
            }
        }
    }
    #undef STAGE
}

// ---------------- combine ----------------
__global__ void k_combine(float* __restrict__ out) {
    int i = blockIdx.x*blockDim.x + threadIdx.x;
    if (i >= TOK*D) return;
    int t = i >> 10;
    int d = i & 1023;
    int s0 = g_slot_of[t*2], s1 = g_slot_of[t*2+1];
    out[i] = g_gw[t*2]   * g_y[(size_t)s0*D + d]
           + g_gw[t*2+1] * g_y[(size_t)s1*D + d];
}

// ---------------- launch ----------------
extern "C" void kernel_launch(void* const* d_in, const int* in_sizes, int n_in,
                              void* d_out, int out_size) {
    const float* x  = (const float*)d_in[0];
    const float* Wg = (const float*)d_in[1];
    const float* W1 = (const float*)d_in[2];
    const float* b1 = (const float*)d_in[3];
    const float* W2 = (const float*)d_in[4];
    const float* b2 = (const float*)d_in[5];
    float* out = (float*)d_out;

    static int attr_done = 0;
    if (!attr_done) {
        cudaFuncSetAttribute(k_gemm1_mma, cudaFuncAttributeMaxDynamicSharedMemorySize, SMEM_BYTES);
        cudaFuncSetAttribute(k_gemm2_mma, cudaFuncAttributeMaxDynamicSharedMemorySize, SMEM_BYTES);
        attr_done = 1;
    }

    k_init<<<(MAXROWS + 255)/256, 256>>>();
    k_gate<<<TOK/8, 256>>>(x, Wg);
    k_offsets<<<1,1>>>(out + (size_t)TOK*D, (out_size > TOK*D) ? 1 : 0);
    k_scatter<<<(TOK*2 + 255)/256, 256>>>();
    k_split_x<<<(TOK*D/4 + 255)/256, 256>>>(x);
    k_tsplit<<<dim3(DFF/32, D/32, E), dim3(32,8)>>>(W1, D, DFF, 0);
    k_tsplit<<<dim3(D/32, DFF/32, E), dim3(32,8)>>>(W2, DFF, D, 1);
    k_gemm1_mma<<<dim3(DFF/BN, NROWT), 256, SMEM_BYTES>>>(b1);
    k_gemm2_mma<<<dim3(D/BN, NROWT), 256, SMEM_BYTES>>>(b2);
    k_combine<<<(TOK*D + 255)/256, 256>>>(out);
}

// round 4
// speedup vs baseline: 2.4373x; 1.0495x over previous
#include <cuda_runtime.h>
#include <cuda_bf16.h>
#include <math.h>
#include <stdint.h>

#define D    1024
#define DFF  4096
#define E    8
#define TOK  8192
#define BM   128             // CTA rows
#define BN   256             // CTA cols
#define BK   32              // bf16 per K chunk
#define STAGES 4
#define ROWB 144             // 64B hi + 64B lo + 16B pad
#define ABLK (BM*ROWB)       // 18432
#define BBLK (BN*ROWB)       // 36864
#define STGB (ABLK+BBLK)     // 55296
#define SMEM_BYTES (STAGES*STGB)   // 221184
#define MAXROWS (2*TOK + E*BM)     // 17408
#define NROWT (MAXROWS/BM)         // 136

// ---------------- scratch ----------------
__device__ int   g_eid[TOK*2];
__device__ float g_gw[TOK*2];
__device__ int   g_counts[E];
__device__ int   g_off[E+1];
__device__ int   g_cursor[E];
__device__ int   g_total;
__device__ int   g_slot_token[MAXROWS];
__device__ int   g_slot_of[TOK*2];
__device__ float g_usage[E];
__device__ __nv_bfloat16 g_xhi[TOK*D],  g_xlo[TOK*D];
__device__ __nv_bfloat16 g_w1hi[E*DFF*D], g_w1lo[E*DFF*D];   // [E][DFF][D]
__device__ __nv_bfloat16 g_w2hi[E*D*DFF], g_w2lo[E*D*DFF];   // [E][D][DFF]
__device__ __nv_bfloat16 g_hhi[(size_t)MAXROWS*DFF], g_hlo[(size_t)MAXROWS*DFF];
__device__ float g_y[(size_t)MAXROWS*D];

// ---------------- helpers ----------------
__device__ __forceinline__ uint32_t smem_u32(const void* p) {
    uint32_t a;
    asm("{ .reg .u64 t; cvta.to.shared.u64 t, %1; cvt.u32.u64 %0, t; }" : "=r"(a) : "l"(p));
    return a;
}
#define CPA(dst, src) asm volatile("cp.async.cg.shared.global [%0], [%1], 16;" :: "r"(dst), "l"(src) : "memory")
#define CPCOMMIT()    asm volatile("cp.async.commit_group;" ::: "memory")
#define CPWAIT(n)     asm volatile("cp.async.wait_group %0;" :: "n"(n) : "memory")
#define MMA(c, a, b) asm volatile( \
    "mma.sync.aligned.m16n8k16.row.col.f32.bf16.bf16.f32 " \
    "{%0,%1,%2,%3},{%4,%5,%6,%7},{%8,%9},{%0,%1,%2,%3};" \
    : "+f"((c)[0]),"+f"((c)[1]),"+f"((c)[2]),"+f"((c)[3]) \
    : "r"((a)[0]),"r"((a)[1]),"r"((a)[2]),"r"((a)[3]),"r"((b)[0]),"r"((b)[1]))

// ---------------- init ----------------
__global__ void k_init() {
    int i = blockIdx.x*blockDim.x + threadIdx.x;
    if (i < MAXROWS) g_slot_token[i] = 0;
    if (i < E) { g_counts[i] = 0; g_usage[i] = 0.f; }
}

// ---------------- gating ----------------
__global__ __launch_bounds__(256) void k_gate(const float* __restrict__ x,
                                              const float* __restrict__ Wg) {
    __shared__ float sWg[E*D];
    for (int i = threadIdx.x; i < E*D; i += blockDim.x) sWg[i] = Wg[i];
    __syncthreads();
    int warp = threadIdx.x >> 5, lane = threadIdx.x & 31;
    int t = blockIdx.x * 8 + warp;
    if (t >= TOK) return;
    const float* xr = x + (size_t)t * D;
    float acc[E];
    #pragma unroll
    for (int e = 0; e < E; e++) acc[e] = 0.f;
    for (int d = lane; d < D; d += 32) {
        float xv = xr[d];
        #pragma unroll
        for (int e = 0; e < E; e++) acc[e] += xv * sWg[e*D + d];
    }
    #pragma unroll
    for (int e = 0; e < E; e++)
        #pragma unroll
        for (int o = 16; o > 0; o >>= 1)
            acc[e] += __shfl_xor_sync(0xffffffffu, acc[e], o);
    if (lane == 0) {
        int i0 = 0; float v0 = acc[0];
        #pragma unroll
        for (int e = 1; e < E; e++) if (acc[e] > v0) { v0 = acc[e]; i0 = e; }
        int i1 = -1; float v1 = -INFINITY;
        #pragma unroll
        for (int e = 0; e < E; e++) if (e != i0 && acc[e] > v1) { v1 = acc[e]; i1 = e; }
        float ex = expf(v1 - v0);
        float inv = 1.f / (1.f + ex);
        g_eid[t*2] = i0; g_eid[t*2+1] = i1;
        g_gw[t*2]  = inv; g_gw[t*2+1] = ex * inv;
        atomicAdd(&g_counts[i0], 1); atomicAdd(&g_counts[i1], 1);
        atomicAdd(&g_usage[i0], inv); atomicAdd(&g_usage[i1], ex*inv);
    }
}

// ---------------- offsets + lb loss ----------------
__global__ void k_offsets(float* loss_out, int write_loss) {
    int off = 0;
    g_off[0] = 0;
    for (int e = 0; e < E; e++) {
        g_cursor[e] = off;
        off += (g_counts[e] + BM - 1) / BM * BM;
        g_off[e+1] = off;
    }
    g_total = off;
    if (write_loss) {
        float u[E]; float mean = 0.f;
        for (int e = 0; e < E; e++) { u[e] = g_usage[e] / (float)TOK; mean += u[e]; }
        mean /= (float)E;
        float var = 0.f;
        for (int e = 0; e < E; e++) { float d = u[e] - mean; var += d * d; }
        var /= (float)(E - 1);
        loss_out[0] = var * 0.01f;
    }
}

// ---------------- scatter ----------------
__global__ void k_scatter() {
    int i = blockIdx.x*blockDim.x + threadIdx.x;
    if (i >= TOK*2) return;
    int e = g_eid[i];
    int pos = atomicAdd(&g_cursor[e], 1);
    g_slot_token[pos] = i >> 1;
    g_slot_of[i] = pos;
}

// ---------------- split x ----------------
__global__ void k_split_x(const float* __restrict__ x) {
    int i = (blockIdx.x*blockDim.x + threadIdx.x) * 4;
    if (i >= TOK*D) return;
    float4 v = *(const float4*)(x + i);
    __nv_bfloat162 h01 = __floats2bfloat162_rn(v.x, v.y);
    __nv_bfloat162 h23 = __floats2bfloat162_rn(v.z, v.w);
    float l0 = v.x - __bfloat162float(__low2bfloat16(h01));
    float l1 = v.y - __bfloat162float(__high2bfloat16(h01));
    float l2 = v.z - __bfloat162float(__low2bfloat16(h23));
    float l3 = v.w - __bfloat162float(__high2bfloat16(h23));
    __nv_bfloat162 lo01 = __floats2bfloat162_rn(l0, l1);
    __nv_bfloat162 lo23 = __floats2bfloat162_rn(l2, l3);
    uint2 ph = make_uint2(*(uint32_t*)&h01, *(uint32_t*)&h23);
    uint2 pl = make_uint2(*(uint32_t*)&lo01, *(uint32_t*)&lo23);
    *(uint2*)((char*)g_xhi + (size_t)i*2) = ph;
    *(uint2*)((char*)g_xlo + (size_t)i*2) = pl;
}

// ---------------- transpose + split weights ----------------
__global__ void k_tsplit(const float* __restrict__ W, int R, int C, int which) {
    __shared__ float t[32][33];
    int e = blockIdx.z;
    int c0 = blockIdx.x * 32, r0 = blockIdx.y * 32;
    int tx = threadIdx.x, ty = threadIdx.y;
    const float* in = W + (size_t)e * R * C;
    #pragma unroll
    for (int i = ty; i < 32; i += 8)
        t[i][tx] = in[(size_t)(r0 + i) * C + c0 + tx];
    __syncthreads();
    __nv_bfloat16* oh = which ? g_w2hi : g_w1hi;
    __nv_bfloat16* ol = which ? g_w2lo : g_w1lo;
    size_t ob = (size_t)e * C * R;
    #pragma unroll
    for (int i = ty; i < 32; i += 8) {
        float v = t[tx][i];
        size_t oi = ob + (size_t)(c0 + i) * R + r0 + tx;
        __nv_bfloat16 h = __float2bfloat16_rn(v);
        oh[oi] = h;
        ol[oi] = __float2bfloat16_rn(v - __bfloat162float(h));
    }
}

// ================= mma.sync GEMMs, 128x256 CTA tile, 64x64 warp tile =================
// stage: [A 128 rows x 144B][B 256 rows x 144B]; row = 64B hi | 64B lo | 16B pad

__global__ void __launch_bounds__(256, 1) k_gemm1_mma(const float* __restrict__ b1) {
    extern __shared__ __align__(128) char smem[];
    __shared__ int stok[BM];
    const int tid = threadIdx.x, wid = tid >> 5, lane = tid & 31;
    const int g = lane >> 2, t4 = lane & 3;
    const int row0 = blockIdx.y * BM;
    if (row0 >= g_total) return;
    int e = 0;
    #pragma unroll
    for (int i = 1; i < E; i++) if (row0 >= g_off[i]) e = i;
    const int n0 = blockIdx.x * BN;
    const int wm = (wid & 1) * 64, wn = (wid >> 1) * 64;

    if (tid < BM) stok[tid] = g_slot_token[row0 + tid];
    __syncthreads();
    const uint32_t sb = smem_u32(smem);

    #define STAGE(st, c) do { \
        uint32_t base = sb + (st)*STGB; \
        int k0 = (c)*BK; \
        _Pragma("unroll") \
        for (int j = 0; j < 4; j++) { \
            int cid = j*256 + tid, row = cid >> 3, grp = cid & 7; \
            const char* src = (grp < 4 ? (const char*)g_xhi : (const char*)g_xlo) \
                              + ((size_t)stok[row]*D + k0)*2 + (grp & 3)*16; \
            CPA(base + row*ROWB + grp*16, src); \
        } \
        _Pragma("unroll") \
        for (int j = 0; j < 8; j++) { \
            int cid = j*256 + tid, row = cid >> 3, grp = cid & 7; \
            const char* src = (grp < 4 ? (const char*)g_w1hi : (const char*)g_w1lo) \
                              + (((size_t)e*DFF + n0 + row)*D + k0)*2 + (grp & 3)*16; \
            CPA(base + ABLK + row*ROWB + grp*16, src); \
        } \
    } while (0)

    const int NC = D / BK;   // 32
    #pragma unroll
    for (int c = 0; c < STAGES-1; c++) { STAGE(c, c); CPCOMMIT(); }

    float acc[4][8][4] = {};
    for (int c = 0; c < NC; c++) {
        CPWAIT(STAGES-2);
        __syncthreads();
        if (c + STAGES-1 < NC) STAGE((c + STAGES-1) & (STAGES-1), c + STAGES-1);
        CPCOMMIT();
        const char* sp = smem + (c & (STAGES-1)) * STGB;
        #pragma unroll
        for (int ks = 0; ks < 2; ks++) {
            uint32_t ah[4][4], al[4][4];
            #pragma unroll
            for (int mt = 0; mt < 4; mt++) {
                const char* p = sp + (wm + mt*16 + g)*ROWB + ks*32 + t4*4;
                ah[mt][0] = *(const uint32_t*)(p);
                ah[mt][1] = *(const uint32_t*)(p + 8*ROWB);
                ah[mt][2] = *(const uint32_t*)(p + 16);
                ah[mt][3] = *(const uint32_t*)(p + 8*ROWB + 16);
                al[mt][0] = *(const uint32_t*)(p + 64);
                al[mt][1] = *(const uint32_t*)(p + 8*ROWB + 64);
                al[mt][2] = *(const uint32_t*)(p + 80);
                al[mt][3] = *(const uint32_t*)(p + 8*ROWB + 80);
            }
            #pragma unroll
            for (int h = 0; h < 2; h++) {
                uint32_t bh[4][2], bl[4][2];
                #pragma unroll
                for (int q = 0; q < 4; q++) {
                    const char* p = sp + ABLK + (wn + (h*4+q)*8 + g)*ROWB + ks*32 + t4*4;
                    bh[q][0] = *(const uint32_t*)(p);
                    bh[q][1] = *(const uint32_t*)(p + 16);
                    bl[q][0] = *(const uint32_t*)(p + 64);
                    bl[q][1] = *(const uint32_t*)(p + 80);
                }
                #pragma unroll
                for (int mt = 0; mt < 4; mt++)
                    #pragma unroll
                    for (int q = 0; q < 4; q++) {
                        MMA(acc[mt][h*4+q], ah[mt], bh[q]);
                        MMA(acc[mt][h*4+q], ah[mt], bl[q]);
                        MMA(acc[mt][h*4+q], al[mt], bh[q]);
                    }
            }
        }
    }

    // epilogue: bias + exact gelu + bf16 split store
    #pragma unroll
    for (int mt = 0; mt < 4; mt++) {
        #pragma unroll
        for (int nt = 0; nt < 8; nt++) {
            int col = n0 + wn + nt*8 + t4*2;
            float bi0 = __ldg(&b1[e*DFF + col]);
            float bi1 = __ldg(&b1[e*DFF + col + 1]);
            #pragma unroll
            for (int h = 0; h < 2; h++) {
                int row = row0 + wm + mt*16 + g + h*8;
                float v0 = acc[mt][nt][2*h]   + bi0;
                float v1 = acc[mt][nt][2*h+1] + bi1;
                float g0 = 0.5f * v0 * (1.f + erff(v0 * 0.7071067811865476f));
                float g1 = 0.5f * v1 * (1.f + erff(v1 * 0.7071067811865476f));
                __nv_bfloat162 hh = __floats2bfloat162_rn(g0, g1);
                float l0 = g0 - __bfloat162float(__low2bfloat16(hh));
                float l1 = g1 - __bfloat162float(__high2bfloat16(hh));
                __nv_bfloat162 ll = __floats2bfloat162_rn(l0, l1);
                size_t o = ((size_t)row * DFF + col) * 2;
                *(uint32_t*)((char*)g_hhi + o) = *(uint32_t*)&hh;
                *(uint32_t*)((char*)g_hlo + o) = *(uint32_t*)&ll;
            }
        }
    }
    #undef STAGE
}

__global__ void __launch_bounds__(256, 1) k_gemm2_mma(const float* __restrict__ b2) {
    extern __shared__ __align__(128) char smem[];
    const int tid = threadIdx.x, wid = tid >> 5, lane = tid & 31;
    const int g = lane >> 2, t4 = lane & 3;
    const int row0 = blockIdx.y * BM;
    if (row0 >= g_total) return;
    int e = 0;
    #pragma unroll
    for (int i = 1; i < E; i++) if (row0 >= g_off[i]) e = i;
    const int n0 = blockIdx.x * BN;
    const int wm = (wid & 1) * 64, wn = (wid >> 1) * 64;
    const uint32_t sb = smem_u32(smem);

    #define STAGE(st, c) do { \
        uint32_t base = sb + (st)*STGB; \
        int k0 = (c)*BK; \
        _Pragma("unroll") \
        for (int j = 0; j < 4; j++) { \
            int cid = j*256 + tid, row = cid >> 3, grp = cid & 7; \
            const char* src = (grp < 4 ? (const char*)g_hhi : (const char*)g_hlo) \
                              + ((size_t)(row0 + row)*DFF + k0)*2 + (grp & 3)*16; \
            CPA(base + row*ROWB + grp*16, src); \
        } \
        _Pragma("unroll") \
        for (int j = 0; j < 8; j++) { \
            int cid = j*256 + tid, row = cid >> 3, grp = cid & 7; \
            const char* src = (grp < 4 ? (const char*)g_w2hi : (const char*)g_w2lo) \
                              + (((size_t)e*D + n0 + row)*DFF + k0)*2 + (grp & 3)*16; \
            CPA(base + ABLK + row*ROWB + grp*16, src); \
        } \
    } while (0)

    const int NC = DFF / BK;   // 128
    #pragma unroll
    for (int c = 0; c < STAGES-1; c++) { STAGE(c, c); CPCOMMIT(); }

    float acc[4][8][4] = {};
    for (int c = 0; c < NC; c++) {
        CPWAIT(STAGES-2);
        __syncthreads();
        if (c + STAGES-1 < NC) STAGE((c + STAGES-1) & (STAGES-1), c + STAGES-1);
        CPCOMMIT();
        const char* sp = smem + (c & (STAGES-1)) * STGB;
        #pragma unroll
        for (int ks = 0; ks < 2; ks++) {
            uint32_t ah[4][4], al[4][4];
            #pragma unroll
            for (int mt = 0; mt < 4; mt++) {
                const char* p = sp + (wm + mt*16 + g)*ROWB + ks*32 + t4*4;
                ah[mt][0] = *(const uint32_t*)(p);
                ah[mt][1] = *(const uint32_t*)(p + 8*ROWB);
                ah[mt][2] = *(const uint32_t*)(p + 16);
                ah[mt][3] = *(const uint32_t*)(p + 8*ROWB + 16);
                al[mt][0] = *(const uint32_t*)(p + 64);
                al[mt][1] = *(const uint32_t*)(p + 8*ROWB + 64);
                al[mt][2] = *(const uint32_t*)(p + 80);
                al[mt][3] = *(const uint32_t*)(p + 8*ROWB + 80);
            }
            #pragma unroll
            for (int h = 0; h < 2; h++) {
                uint32_t bh[4][2], bl[4][2];
                #pragma unroll
                for (int q = 0; q < 4; q++) {
                    const char* p = sp + ABLK + (wn + (h*4+q)*8 + g)*ROWB + ks*32 + t4*4;
                    bh[q][0] = *(const uint32_t*)(p);
                    bh[q][1] = *(const uint32_t*)(p + 16);
                    bl[q][0] = *(const uint32_t*)(p + 64);
                    bl[q][1] = *(const uint32_t*)(p + 80);
                }
                #pragma unroll
                for (int mt = 0; mt < 4; mt++)
                    #pragma unroll
                    for (int q = 0; q < 4; q++) {
                        MMA(acc[mt][h*4+q], ah[mt], bh[q]);
                        MMA(acc[mt][h*4+q], ah[mt], bl[q]);
                        MMA(acc[mt][h*4+q], al[mt], bh[q]);
                    }
            }
        }
    }

    #pragma unroll
    for (int mt = 0; mt < 4; mt++) {
        #pragma unroll
        for (int nt = 0; nt < 8; nt++) {
            int col = n0 + wn + nt*8 + t4*2;
            float bi0 = __ldg(&b2[e*D + col]);
            float bi1 = __ldg(&b2[e*D + col + 1]);
            #pragma unroll
            for (int h = 0; h < 2; h++) {
                int row = row0 + wm + mt*16 + g + h*8;
                float2 v = make_float2(acc[mt][nt][2*h] + bi0, acc[mt][nt][2*h+1] + bi1);
                *(float2*)(g_y + (size_t)row * D + col) = v;
            }
        }
    }
    #undef STAGE
}

// ---------------- combine ----------------
__global__ void k_combine(float* __restrict__ out) {
    int i = blockIdx.x*blockDim.x + threadIdx.x;
    if (i >= TOK*D) return;
    int t = i >> 10;
    int d = i & 1023;
    int s0 = g_slot_of[t*2], s1 = g_slot_of[t*2+1];
    out[i] = g_gw[t*2]   * g_y[(size_t)s0*D + d]
           + g_gw[t*2+1] * g_y[(size_t)s1*D + d];
}

// ---------------- launch ----------------
extern "C" void kernel_launch(void* const* d_in, const int* in_sizes, int n_in,
                              void* d_out, int out_size) {
    const float* x  = (const float*)d_in[0];
    const float* Wg = (const float*)d_in[1];
    const float* W1 = (const float*)d_in[2];
    const float* b1 = (const float*)d_in[3];
    const float* W2 = (const float*)d_in[4];
    const float* b2 = (const float*)d_in[5];
    float* out = (float*)d_out;

    cudaFuncSetAttribute(k_gemm1_mma, cudaFuncAttributeMaxDynamicSharedMemorySize, SMEM_BYTES);
    cudaFuncSetAttribute(k_gemm2_mma, cudaFuncAttributeMaxDynamicSharedMemorySize, SMEM_BYTES);

    k_init<<<(MAXROWS + 255)/256, 256>>>();
    k_gate<<<TOK/8, 256>>>(x, Wg);
    k_offsets<<<1,1>>>(out + (size_t)TOK*D, (out_size > TOK*D) ? 1 : 0);
    k_scatter<<<(TOK*2 + 255)/256, 256>>>();
    k_split_x<<<(TOK*D/4 + 255)/256, 256>>>(x);
    k_tsplit<<<dim3(DFF/32, D/32, E), dim3(32,8)>>>(W1, D, DFF, 0);
    k_tsplit<<<dim3(D/32, DFF/32, E), dim3(32,8)>>>(W2, DFF, D, 1);
    k_gemm1_mma<<<dim3(DFF/BN, NROWT), 256, SMEM_BYTES>>>(b1);
    k_gemm2_mma<<<dim3(D/BN, NROWT), 256, SMEM_BYTES>>>(b2);
    k_combine<<<(TOK*D + 255)/256, 256>>>(out);
}